// round 4
// baseline (speedup 1.0000x reference)
#include <cuda_runtime.h>
#include <math.h>

// Problem constants (from reference): G=4096 grid, C=8 channels, N=4 batch.
constexpr int G  = 4096;
constexpr int C  = 8;
constexpr int NB = 4;
constexpr int T  = 256;        // threads per block
constexpr int L  = G / T;      // 16 elements per thread
constexpr int WARPS = T / 32;  // 8

// out[n,c,i] = 0.5*a_c*dx * sum_j d[n,j] * exp(-|i-j|*dx*a_c),  a_c = 1 + exp(-xi_c)
// Forward/backward first-order linear recurrences with ratio r = exp(-dx*a).
// Latency-optimized: tree aggregates feed the warp scan early; serial local
// scans and weight tables compute in the shadow of the shfl scan + barrier.
__global__ __launch_bounds__(T, 1)
void gconv_scan_kernel(const float* __restrict__ density,
                       const float* __restrict__ xi,
                       const float* __restrict__ grid,
                       float* __restrict__ out)
{
    const int nc   = blockIdx.x;        // 0..N*C-1
    const int n    = nc / C;
    const int c    = nc % C;
    const int tid  = threadIdx.x;
    const int lane = tid & 31;
    const int warp = tid >> 5;

    __shared__ float sWf[WARPS];
    __shared__ float sWb[WARPS];

    // ---- issue density loads FIRST so DRAM latency overlaps constant setup ----
    const float4* d4 = (const float4*)(density + (size_t)n * G + (size_t)tid * L);
    float4 v0 = d4[0], v1 = d4[1], v2 = d4[2], v3 = d4[3];

    // ---- scalar setup (MUFU.EX2 path; all args |x| <= ~0.25) ----
    const float dx   = grid[1] - grid[0];
    const float a    = 1.0f + __expf(-xi[c]);    // xi_eff = 1/sigmoid(xi)
    const float dxa  = dx * a;
    const float r    = __expf(-dxa);                         // r^1
    const float RL   = __expf(-dxa * (float)L);              // r^L
    const float R32L = __expf(-dxa * (float)(32 * L));       // r^{32L}
    const float pf   = __expf(-dxa * (float)(lane * L));        // bridge powers
    const float pb   = __expf(-dxa * (float)((31 - lane) * L));
    const float invRL = 1.0f / RL;       // RL in [0.99,1): safe; computed off-path
    const float r2 = r * r, r4 = r2 * r2, r8 = r4 * r4;

    float d[L];
    d[0]=v0.x; d[1]=v0.y; d[2]=v0.z; d[3]=v0.w;
    d[4]=v1.x; d[5]=v1.y; d[6]=v1.z; d[7]=v1.w;
    d[8]=v2.x; d[9]=v2.y; d[10]=v2.z; d[11]=v2.w;
    d[12]=v3.x; d[13]=v3.y; d[14]=v3.z; d[15]=v3.w;

    // ---- chunk aggregates via log-depth trees (critical path feeder) ----
    // aggF = sum_k d[k] * r^{15-k};  aggB = sum_k d[k] * r^k
    float aggF, aggB;
    {
        float tf[8], tb[8];
        #pragma unroll
        for (int j = 0; j < 8; j++) {
            tf[j] = fmaf(r, d[2*j],     d[2*j+1]);   // weight older by r
            tb[j] = fmaf(r, d[2*j+1],   d[2*j]);
        }
        float uf[4], ub[4];
        #pragma unroll
        for (int j = 0; j < 4; j++) {
            uf[j] = fmaf(r2, tf[2*j],   tf[2*j+1]);
            ub[j] = fmaf(r2, tb[2*j+1], tb[2*j]);
        }
        float wf0 = fmaf(r4, uf[0], uf[1]);
        float wf1 = fmaf(r4, uf[2], uf[3]);
        float wb0 = fmaf(r4, ub[1], ub[0]);
        float wb1 = fmaf(r4, ub[3], ub[2]);
        aggF = fmaf(r8, wf0, wf1);
        aggB = fmaf(r8, wb1, wb0);
    }

    // ---- warp-level inclusive scans of chunk aggregates (ratio RL) ----
    float vf = aggF, vb = aggB;
    float Rp = RL;
    #pragma unroll
    for (int off = 1; off < 32; off <<= 1) {
        float uf = __shfl_up_sync(0xffffffffu, vf, off);
        float ub = __shfl_down_sync(0xffffffffu, vb, off);
        if (lane >= off)      vf = fmaf(Rp, uf, vf);
        if (lane < 32 - off)  vb = fmaf(Rp, ub, vb);
        Rp *= Rp;  // RL^{2^i}
    }

    if (lane == 31) sWf[warp] = vf;   // whole-warp forward aggregate
    if (lane == 0)  sWb[warp] = vb;   // whole-warp backward aggregate

    // ---- work hidden under the scan/barrier: local scans + weight table ----
    float lf[L], lb[L];
    {
        float s = 0.f;
        #pragma unroll
        for (int k = 0; k < L; k++) { s = fmaf(r, s, d[k]); lf[k] = s; }
    }
    {
        float s = 0.f;
        #pragma unroll
        for (int k = L - 1; k >= 0; k--) { s = fmaf(r, s, d[k]); lb[k] = s; }
    }
    float rk[L];                 // rk[k] = r^{k+1}; backward weight r^{L-k} = rk[L-1-k]
    rk[0] = r;
    #pragma unroll
    for (int k = 1; k < L; k++) rk[k] = rk[k-1] * r;

    __syncthreads();

    // ---- cross-warp carries (<= 8 serial fma's, computed redundantly per thread) ----
    float cwf = 0.f;
    #pragma unroll
    for (int u = 0; u < WARPS; u++)
        if (u < warp) cwf = fmaf(R32L, cwf, sWf[u]);
    float cwb = 0.f;
    #pragma unroll
    for (int u = WARPS - 1; u >= 0; u--)
        if (u > warp) cwb = fmaf(R32L, cwb, sWb[u]);

    // exclusive within-warp prefixes, algebraically (no trailing shfl):
    // vf = aggF + RL * ef  =>  ef = (vf - aggF) / RL
    const float ef = (vf - aggF) * invRL;
    const float eb = (vb - aggB) * invRL;

    const float carryF = fmaf(pf, cwf, ef);  // S_f at (chunk base - 1)
    const float carryB = fmaf(pb, cwb, eb);  // S_b at (chunk base + L)

    // ---- apply carries with precomputed powers (depth-1) + combine + write ----
    const float scale = 0.5f * a * dx;
    float4* optr = (float4*)(out + (size_t)nc * G + (size_t)tid * L);
    #pragma unroll
    for (int q = 0; q < L / 4; q++) {
        float4 v;
        #pragma unroll
        for (int e = 0; e < 4; e++) {
            const int k = 4*q + e;
            const float sf = fmaf(rk[k],       carryF, lf[k]);
            const float sb = fmaf(rk[L-1-k],   carryB, lb[k]);
            ((float*)&v)[e] = scale * (sf + sb - d[k]);
        }
        optr[q] = v;
    }
}

extern "C" void kernel_launch(void* const* d_in, const int* in_sizes, int n_in,
                              void* d_out, int out_size)
{
    const float* density = (const float*)d_in[0];  // (N,1,G)
    const float* xi      = (const float*)d_in[1];  // (C,)
    const float* grid    = (const float*)d_in[2];  // (G,)
    float*       out     = (float*)d_out;          // (N,C,G)

    gconv_scan_kernel<<<NB * C, T>>>(density, xi, grid, out);
}

// round 5
// speedup vs baseline: 1.0370x; 1.0370x over previous
#include <cuda_runtime.h>
#include <math.h>

// Problem constants (from reference): G=4096 grid, C=8 channels, N=4 batch.
constexpr int G  = 4096;
constexpr int C  = 8;
constexpr int NB = 4;
constexpr int T  = 256;        // threads per block
constexpr int L  = G / T;      // 16 elements per thread
constexpr int WARPS = T / 32;  // 8

// out[n,c,i] = 0.5*a_c*dx * sum_j d[n,j] * exp(-|i-j|*dx*a_c)
// a_c = 1/sigmoid(xi_c) = 1 + exp(-xi_c)
// Forward/backward first-order linear recurrences with ratio r = exp(-dx*a),
// 3-level segmented scan (thread chunk -> warp shfl scan -> cross-warp smem).
// __expf (MUFU.EX2) is safe here: all exponent args have |x| <= ~0.25.
__global__ __launch_bounds__(T, 1)
void gconv_scan_kernel(const float* __restrict__ density,
                       const float* __restrict__ xi,
                       const float* __restrict__ grid,
                       float* __restrict__ out)
{
    const int nc   = blockIdx.x;        // 0..N*C-1
    const int n    = nc / C;
    const int c    = nc % C;
    const int tid  = threadIdx.x;
    const int lane = tid & 31;
    const int warp = tid >> 5;

    __shared__ float sWf[WARPS];
    __shared__ float sWb[WARPS];

    // ---- issue density loads FIRST so DRAM latency overlaps constant setup ----
    const float4* d4 = (const float4*)(density + (size_t)n * G + (size_t)tid * L);
    float4 v0 = d4[0], v1 = d4[1], v2 = d4[2], v3 = d4[3];

    // ---- scalar setup (fast intrinsics; args tiny so EX2 approx is ~2^-22 rel) ----
    const float dx   = grid[1] - grid[0];
    const float a    = 1.0f + __expf(-xi[c]);    // xi_eff = 1/sigmoid(xi)
    const float dxa  = dx * a;
    const float r    = __expf(-dxa);                         // r^1
    const float RL   = __expf(-dxa * (float)L);              // r^L
    const float R32L = __expf(-dxa * (float)(32 * L));       // r^{32L}
    // bridge powers for carry injection (direct, no product drift)
    const float pf = __expf(-dxa * (float)(lane * L));
    const float pb = __expf(-dxa * (float)((31 - lane) * L));

    float d[L];
    d[0]=v0.x; d[1]=v0.y; d[2]=v0.z; d[3]=v0.w;
    d[4]=v1.x; d[5]=v1.y; d[6]=v1.z; d[7]=v1.w;
    d[8]=v2.x; d[9]=v2.y; d[10]=v2.z; d[11]=v2.w;
    d[12]=v3.x; d[13]=v3.y; d[14]=v3.z; d[15]=v3.w;

    // ---- local (per-thread) forward and backward scans (two independent chains) ----
    float lf[L], lb[L];
    {
        float s = 0.f;
        #pragma unroll
        for (int k = 0; k < L; k++) { s = fmaf(r, s, d[k]); lf[k] = s; }
    }
    {
        float s = 0.f;
        #pragma unroll
        for (int k = L - 1; k >= 0; k--) { s = fmaf(r, s, d[k]); lb[k] = s; }
    }

    // ---- warp-level inclusive scans of chunk aggregates (ratio RL) ----
    float vf = lf[L - 1];   // forward aggregate of this chunk
    float vb = lb[0];       // backward aggregate of this chunk
    float Rp = RL;
    #pragma unroll
    for (int off = 1; off < 32; off <<= 1) {
        float uf = __shfl_up_sync(0xffffffffu, vf, off);
        float ub = __shfl_down_sync(0xffffffffu, vb, off);
        if (lane >= off)      vf = fmaf(Rp, uf, vf);
        if (lane < 32 - off)  vb = fmaf(Rp, ub, vb);
        Rp *= Rp;  // RL^{2^i}
    }

    if (lane == 31) sWf[warp] = vf;   // whole-warp forward aggregate
    if (lane == 0)  sWb[warp] = vb;   // whole-warp backward aggregate
    __syncthreads();

    // ---- cross-warp carries (<= 8 serial fma's, computed redundantly per thread) ----
    float cwf = 0.f;
    #pragma unroll
    for (int u = 0; u < WARPS; u++)
        if (u < warp) cwf = fmaf(R32L, cwf, sWf[u]);
    float cwb = 0.f;
    #pragma unroll
    for (int u = WARPS - 1; u >= 0; u--)
        if (u > warp) cwb = fmaf(R32L, cwb, sWb[u]);

    // exclusive within-warp prefixes
    float ef = __shfl_up_sync(0xffffffffu, vf, 1);
    if (lane == 0)  ef = 0.f;
    float eb = __shfl_down_sync(0xffffffffu, vb, 1);
    if (lane == 31) eb = 0.f;

    const float carryF = fmaf(pf, cwf, ef);  // S_f at (chunk base - 1)
    const float carryB = fmaf(pb, cwb, eb);  // S_b at (chunk base + L)

    // ---- apply carries: S_f[k] += r^{k+1}*carryF ; S_b[k] += r^{L-k}*carryB ----
    {
        float w = r;
        #pragma unroll
        for (int k = 0; k < L; k++) { lf[k] = fmaf(w, carryF, lf[k]); w *= r; }
    }
    {
        float w = r;
        #pragma unroll
        for (int k = L - 1; k >= 0; k--) { lb[k] = fmaf(w, carryB, lb[k]); w *= r; }
    }

    // ---- combine + write (128-bit stores) ----
    const float scale = 0.5f * a * dx;
    float4* optr = (float4*)(out + (size_t)nc * G + (size_t)tid * L);
    #pragma unroll
    for (int q = 0; q < L / 4; q++) {
        float4 v;
        v.x = scale * (lf[4*q+0] + lb[4*q+0] - d[4*q+0]);
        v.y = scale * (lf[4*q+1] + lb[4*q+1] - d[4*q+1]);
        v.z = scale * (lf[4*q+2] + lb[4*q+2] - d[4*q+2]);
        v.w = scale * (lf[4*q+3] + lb[4*q+3] - d[4*q+3]);
        optr[q] = v;
    }
}

extern "C" void kernel_launch(void* const* d_in, const int* in_sizes, int n_in,
                              void* d_out, int out_size)
{
    const float* density = (const float*)d_in[0];  // (N,1,G)
    const float* xi      = (const float*)d_in[1];  // (C,)
    const float* grid    = (const float*)d_in[2];  // (G,)
    float*       out     = (float*)d_out;          // (N,C,G)

    gconv_scan_kernel<<<NB * C, T>>>(density, xi, grid, out);
}

// round 6
// speedup vs baseline: 1.0467x; 1.0093x over previous
#include <cuda_runtime.h>
#include <math.h>

// Problem constants (from reference): G=4096 grid, C=8 channels, N=4 batch.
constexpr int G  = 4096;
constexpr int C  = 8;
constexpr int NB = 4;
constexpr int T  = 512;        // threads per block
constexpr int L  = G / T;      // 8 elements per thread
constexpr int WARPS = T / 32;  // 16

// out[n,c,i] = 0.5*a_c*dx * sum_j d[n,j] * exp(-|i-j|*dx*a_c)
// a_c = 1/sigmoid(xi_c) = 1 + exp(-xi_c)
// Forward/backward first-order linear recurrences with ratio r = exp(-dx*a),
// 3-level segmented scan (thread chunk -> warp shfl scan -> cross-warp smem).
// __expf (MUFU.EX2) is safe here: all exponent args have |x| <= ~0.25.
__global__ __launch_bounds__(T, 1)
void gconv_scan_kernel(const float* __restrict__ density,
                       const float* __restrict__ xi,
                       const float* __restrict__ grid,
                       float* __restrict__ out)
{
    const int nc   = blockIdx.x;        // 0..N*C-1
    const int n    = nc / C;
    const int c    = nc % C;
    const int tid  = threadIdx.x;
    const int lane = tid & 31;
    const int warp = tid >> 5;

    __shared__ float sWf[WARPS];
    __shared__ float sWb[WARPS];

    // ---- issue density loads FIRST so DRAM latency overlaps constant setup ----
    const float4* d4 = (const float4*)(density + (size_t)n * G + (size_t)tid * L);
    float4 v0 = d4[0], v1 = d4[1];

    // ---- scalar setup (fast intrinsics; args tiny so EX2 approx is ~2^-22 rel) ----
    const float dx   = grid[1] - grid[0];
    const float a    = 1.0f + __expf(-xi[c]);    // xi_eff = 1/sigmoid(xi)
    const float dxa  = dx * a;
    const float r    = __expf(-dxa);                         // r^1
    const float RL   = __expf(-dxa * (float)L);              // r^L
    const float R32L = __expf(-dxa * (float)(32 * L));       // r^{32L}
    // bridge powers for carry injection (direct, no product drift)
    const float pf = __expf(-dxa * (float)(lane * L));
    const float pb = __expf(-dxa * (float)((31 - lane) * L));

    float d[L];
    d[0]=v0.x; d[1]=v0.y; d[2]=v0.z; d[3]=v0.w;
    d[4]=v1.x; d[5]=v1.y; d[6]=v1.z; d[7]=v1.w;

    // ---- local (per-thread) forward and backward scans (two independent chains) ----
    float lf[L], lb[L];
    {
        float s = 0.f;
        #pragma unroll
        for (int k = 0; k < L; k++) { s = fmaf(r, s, d[k]); lf[k] = s; }
    }
    {
        float s = 0.f;
        #pragma unroll
        for (int k = L - 1; k >= 0; k--) { s = fmaf(r, s, d[k]); lb[k] = s; }
    }

    // ---- warp-level inclusive scans of chunk aggregates (ratio RL) ----
    float vf = lf[L - 1];   // forward aggregate of this chunk
    float vb = lb[0];       // backward aggregate of this chunk
    float Rp = RL;
    #pragma unroll
    for (int off = 1; off < 32; off <<= 1) {
        float uf = __shfl_up_sync(0xffffffffu, vf, off);
        float ub = __shfl_down_sync(0xffffffffu, vb, off);
        if (lane >= off)      vf = fmaf(Rp, uf, vf);
        if (lane < 32 - off)  vb = fmaf(Rp, ub, vb);
        Rp *= Rp;  // RL^{2^i}
    }

    if (lane == 31) sWf[warp] = vf;   // whole-warp forward aggregate
    if (lane == 0)  sWb[warp] = vb;   // whole-warp backward aggregate
    __syncthreads();

    // ---- cross-warp carries (<= 16 serial fma's, computed redundantly per thread) ----
    float cwf = 0.f;
    #pragma unroll
    for (int u = 0; u < WARPS; u++)
        if (u < warp) cwf = fmaf(R32L, cwf, sWf[u]);
    float cwb = 0.f;
    #pragma unroll
    for (int u = WARPS - 1; u >= 0; u--)
        if (u > warp) cwb = fmaf(R32L, cwb, sWb[u]);

    // exclusive within-warp prefixes
    float ef = __shfl_up_sync(0xffffffffu, vf, 1);
    if (lane == 0)  ef = 0.f;
    float eb = __shfl_down_sync(0xffffffffu, vb, 1);
    if (lane == 31) eb = 0.f;

    const float carryF = fmaf(pf, cwf, ef);  // S_f at (chunk base - 1)
    const float carryB = fmaf(pb, cwb, eb);  // S_b at (chunk base + L)

    // ---- apply carries: S_f[k] += r^{k+1}*carryF ; S_b[k] += r^{L-k}*carryB ----
    {
        float w = r;
        #pragma unroll
        for (int k = 0; k < L; k++) { lf[k] = fmaf(w, carryF, lf[k]); w *= r; }
    }
    {
        float w = r;
        #pragma unroll
        for (int k = L - 1; k >= 0; k--) { lb[k] = fmaf(w, carryB, lb[k]); w *= r; }
    }

    // ---- combine + write (128-bit stores) ----
    const float scale = 0.5f * a * dx;
    float4* optr = (float4*)(out + (size_t)nc * G + (size_t)tid * L);
    #pragma unroll
    for (int q = 0; q < L / 4; q++) {
        float4 v;
        v.x = scale * (lf[4*q+0] + lb[4*q+0] - d[4*q+0]);
        v.y = scale * (lf[4*q+1] + lb[4*q+1] - d[4*q+1]);
        v.z = scale * (lf[4*q+2] + lb[4*q+2] - d[4*q+2]);
        v.w = scale * (lf[4*q+3] + lb[4*q+3] - d[4*q+3]);
        optr[q] = v;
    }
}

extern "C" void kernel_launch(void* const* d_in, const int* in_sizes, int n_in,
                              void* d_out, int out_size)
{
    const float* density = (const float*)d_in[0];  // (N,1,G)
    const float* xi      = (const float*)d_in[1];  // (C,)
    const float* grid    = (const float*)d_in[2];  // (G,)
    float*       out     = (float*)d_out;          // (N,C,G)

    gconv_scan_kernel<<<NB * C, T>>>(density, xi, grid, out);
}

// round 7
// speedup vs baseline: 1.0821x; 1.0338x over previous
#include <cuda_runtime.h>
#include <math.h>

// FINAL — converged at the launch-latency floor (see R1-R6 journal).
// Problem constants (from reference): G=4096 grid, C=8 channels, N=4 batch.
constexpr int G  = 4096;
constexpr int C  = 8;
constexpr int NB = 4;
constexpr int T  = 256;        // threads per block
constexpr int L  = G / T;      // 16 elements per thread
constexpr int WARPS = T / 32;  // 8

// out[n,c,i] = 0.5*a_c*dx * sum_j d[n,j] * exp(-|i-j|*dx*a_c)
// a_c = 1/sigmoid(xi_c) = 1 + exp(-xi_c)
// Forward/backward first-order linear recurrences with ratio r = exp(-dx*a),
// 3-level segmented scan (thread chunk -> warp shfl scan -> cross-warp smem).
// __expf (MUFU.EX2) is safe here: all exponent args have |x| <= ~0.25.
__global__ __launch_bounds__(T, 1)
void gconv_scan_kernel(const float* __restrict__ density,
                       const float* __restrict__ xi,
                       const float* __restrict__ grid,
                       float* __restrict__ out)
{
    const int nc   = blockIdx.x;        // 0..N*C-1
    const int n    = nc / C;
    const int c    = nc % C;
    const int tid  = threadIdx.x;
    const int lane = tid & 31;
    const int warp = tid >> 5;

    __shared__ float sWf[WARPS];
    __shared__ float sWb[WARPS];

    // ---- issue density loads FIRST so DRAM latency overlaps constant setup ----
    const float4* d4 = (const float4*)(density + (size_t)n * G + (size_t)tid * L);
    float4 v0 = d4[0], v1 = d4[1], v2 = d4[2], v3 = d4[3];

    // ---- scalar setup (fast intrinsics; args tiny so EX2 approx is ~2^-22 rel) ----
    const float dx   = grid[1] - grid[0];
    const float a    = 1.0f + __expf(-xi[c]);    // xi_eff = 1/sigmoid(xi)
    const float dxa  = dx * a;
    const float r    = __expf(-dxa);                         // r^1
    const float RL   = __expf(-dxa * (float)L);              // r^L
    const float R32L = __expf(-dxa * (float)(32 * L));       // r^{32L}
    // bridge powers for carry injection (direct, no product drift)
    const float pf = __expf(-dxa * (float)(lane * L));
    const float pb = __expf(-dxa * (float)((31 - lane) * L));

    float d[L];
    d[0]=v0.x; d[1]=v0.y; d[2]=v0.z; d[3]=v0.w;
    d[4]=v1.x; d[5]=v1.y; d[6]=v1.z; d[7]=v1.w;
    d[8]=v2.x; d[9]=v2.y; d[10]=v2.z; d[11]=v2.w;
    d[12]=v3.x; d[13]=v3.y; d[14]=v3.z; d[15]=v3.w;

    // ---- local (per-thread) forward and backward scans (two independent chains) ----
    float lf[L], lb[L];
    {
        float s = 0.f;
        #pragma unroll
        for (int k = 0; k < L; k++) { s = fmaf(r, s, d[k]); lf[k] = s; }
    }
    {
        float s = 0.f;
        #pragma unroll
        for (int k = L - 1; k >= 0; k--) { s = fmaf(r, s, d[k]); lb[k] = s; }
    }

    // ---- warp-level inclusive scans of chunk aggregates (ratio RL) ----
    float vf = lf[L - 1];   // forward aggregate of this chunk
    float vb = lb[0];       // backward aggregate of this chunk
    float Rp = RL;
    #pragma unroll
    for (int off = 1; off < 32; off <<= 1) {
        float uf = __shfl_up_sync(0xffffffffu, vf, off);
        float ub = __shfl_down_sync(0xffffffffu, vb, off);
        if (lane >= off)      vf = fmaf(Rp, uf, vf);
        if (lane < 32 - off)  vb = fmaf(Rp, ub, vb);
        Rp *= Rp;  // RL^{2^i}
    }

    if (lane == 31) sWf[warp] = vf;   // whole-warp forward aggregate
    if (lane == 0)  sWb[warp] = vb;   // whole-warp backward aggregate
    __syncthreads();

    // ---- cross-warp carries (<= 8 serial fma's, computed redundantly per thread) ----
    float cwf = 0.f;
    #pragma unroll
    for (int u = 0; u < WARPS; u++)
        if (u < warp) cwf = fmaf(R32L, cwf, sWf[u]);
    float cwb = 0.f;
    #pragma unroll
    for (int u = WARPS - 1; u >= 0; u--)
        if (u > warp) cwb = fmaf(R32L, cwb, sWb[u]);

    // exclusive within-warp prefixes
    float ef = __shfl_up_sync(0xffffffffu, vf, 1);
    if (lane == 0)  ef = 0.f;
    float eb = __shfl_down_sync(0xffffffffu, vb, 1);
    if (lane == 31) eb = 0.f;

    const float carryF = fmaf(pf, cwf, ef);  // S_f at (chunk base - 1)
    const float carryB = fmaf(pb, cwb, eb);  // S_b at (chunk base + L)

    // ---- apply carries: S_f[k] += r^{k+1}*carryF ; S_b[k] += r^{L-k}*carryB ----
    {
        float w = r;
        #pragma unroll
        for (int k = 0; k < L; k++) { lf[k] = fmaf(w, carryF, lf[k]); w *= r; }
    }
    {
        float w = r;
        #pragma unroll
        for (int k = L - 1; k >= 0; k--) { lb[k] = fmaf(w, carryB, lb[k]); w *= r; }
    }

    // ---- combine + write (128-bit stores) ----
    const float scale = 0.5f * a * dx;
    float4* optr = (float4*)(out + (size_t)nc * G + (size_t)tid * L);
    #pragma unroll
    for (int q = 0; q < L / 4; q++) {
        float4 v;
        v.x = scale * (lf[4*q+0] + lb[4*q+0] - d[4*q+0]);
        v.y = scale * (lf[4*q+1] + lb[4*q+1] - d[4*q+1]);
        v.z = scale * (lf[4*q+2] + lb[4*q+2] - d[4*q+2]);
        v.w = scale * (lf[4*q+3] + lb[4*q+3] - d[4*q+3]);
        optr[q] = v;
    }
}

extern "C" void kernel_launch(void* const* d_in, const int* in_sizes, int n_in,
                              void* d_out, int out_size)
{
    const float* density = (const float*)d_in[0];  // (N,1,G)
    const float* xi      = (const float*)d_in[1];  // (C,)
    const float* grid    = (const float*)d_in[2];  // (G,)
    float*       out     = (float*)d_out;          // (N,C,G)

    gconv_scan_kernel<<<NB * C, T>>>(density, xi, grid, out);
}